// round 1
// baseline (speedup 1.0000x reference)
#include <cuda_runtime.h>
#include <cuda_bf16.h>
#include <math.h>

#define NATOMS 50000
#define NEDGE  600000
#define HDIM   128
#define NGAUSS 50
#define NLAYER 6
#define NCONF  500
#define NMOL   100
#define TTAB   8192
#define DCUT   13.0f

// ------------------- static device scratch (no allocs allowed) -------------------
__device__ float g_h[NATOMS * HDIM];
__device__ float g_xf[NATOMS * HDIM];
__device__ float g_agg[NATOMS * HDIM];
__device__ float g_u[NATOMS * HDIM];
__device__ float g_U[NLAYER * TTAB * HDIM];    // ssp(gauss@w1+b1)
__device__ float g_tab[NLAYER * TTAB * HDIM];  // W table (incl. cosine cutoff)
__device__ float g_t[NEDGE];                   // table position per edge, -1 = inactive
__device__ int   g_cnt[NATOMS];
__device__ int   g_rowptr[NATOMS + 1];
__device__ int   g_cursor[NATOMS];
__device__ int   g_src[NEDGE];
__device__ float g_et[NEDGE];
__device__ float g_mol[NMOL * HDIM];

__device__ __forceinline__ float sspf(float x) {
    // shifted softplus, matches max(x,0)+log1p(exp(-|x|)) - log(2)
    return fmaxf(x, 0.0f) + log1pf(expf(-fabsf(x))) - 0.69314718055994531f;
}

// ------------------- embedding gather -------------------
__global__ void k_embed(const int* __restrict__ z, const float* __restrict__ emb,
                        float* __restrict__ h) {
    int idx = blockIdx.x * blockDim.x + threadIdx.x;
    if (idx >= NATOMS * HDIM) return;
    int a = idx >> 7, f = idx & 127;
    h[idx] = emb[z[a] * HDIM + f];
}

// ------------------- edge distances + histogram -------------------
__global__ void k_dist(const float* __restrict__ pos, const int* __restrict__ erow,
                       const int* __restrict__ ecol, float* __restrict__ tpos,
                       int* __restrict__ cnt) {
    int e = blockIdx.x * blockDim.x + threadIdx.x;
    if (e >= NEDGE) return;
    int r = erow[e], c = ecol[e];
    float dx = pos[r * 3 + 0] - pos[c * 3 + 0];
    float dy = pos[r * 3 + 1] - pos[c * 3 + 1];
    float dz = pos[r * 3 + 2] - pos[c * 3 + 2];
    float d = sqrtf(dx * dx + dy * dy + dz * dz);
    if (d < DCUT) {
        tpos[e] = d * ((float)(TTAB - 1) / DCUT);
        atomicAdd(&cnt[c], 1);
    } else {
        tpos[e] = -1.0f;
    }
}

// ------------------- single-block exclusive scan over N counts -------------------
__global__ void k_scan(const int* __restrict__ cnt, int* __restrict__ rowptr,
                       int* __restrict__ cursor) {
    __shared__ int sm[1024];
    __shared__ int base_s;
    int tid = threadIdx.x;
    if (tid == 0) base_s = 0;
    __syncthreads();
    for (int c0 = 0; c0 < NATOMS; c0 += 1024) {
        int i = c0 + tid;
        int v = (i < NATOMS) ? cnt[i] : 0;
        sm[tid] = v;
        __syncthreads();
        for (int off = 1; off < 1024; off <<= 1) {
            int t = (tid >= off) ? sm[tid - off] : 0;
            __syncthreads();
            sm[tid] += t;
            __syncthreads();
        }
        int incl = sm[tid];
        int base = base_s;
        if (i < NATOMS) {
            int ex = base + incl - v;
            rowptr[i] = ex;
            cursor[i] = ex;
        }
        __syncthreads();
        if (tid == 1023) base_s = base + incl;
        __syncthreads();
    }
    if (tid == 0) rowptr[NATOMS] = base_s;
}

// ------------------- CSR fill -------------------
__global__ void k_fill(const int* __restrict__ erow, const int* __restrict__ ecol,
                       const float* __restrict__ tpos, int* __restrict__ cursor,
                       int* __restrict__ src, float* __restrict__ et) {
    int e = blockIdx.x * blockDim.x + threadIdx.x;
    if (e >= NEDGE) return;
    float t = tpos[e];
    if (t >= 0.0f) {
        int c = ecol[e];
        int p = atomicAdd(&cursor[c], 1);
        src[p] = erow[e];
        et[p] = t;
    }
}

// ------------------- filter table stage1: U = ssp(gauss @ w1 + b1) -------------------
#define S1ROWS 16
__global__ void k_stage1(const float* __restrict__ mlp_w1, const float* __restrict__ mlp_b1,
                         float* __restrict__ U) {
    __shared__ float w1s[NGAUSS][HDIM];
    __shared__ float gs[S1ROWS][NGAUSS];
    const int blocksPerLayer = TTAB / S1ROWS;
    int l = blockIdx.x / blocksPerLayer;
    int t0 = (blockIdx.x % blocksPerLayer) * S1ROWS;
    const float* w1 = mlp_w1 + l * NGAUSS * HDIM;
    for (int i = threadIdx.x; i < NGAUSS * HDIM; i += blockDim.x)
        w1s[i / HDIM][i % HDIM] = w1[i];
    const float step = 10.0f / 49.0f;
    const float coeff = -0.5f / (step * step);
    for (int i = threadIdx.x; i < S1ROWS * NGAUSS; i += blockDim.x) {
        int r = i / NGAUSS, g = i % NGAUSS;
        float d = (float)(t0 + r) * (DCUT / (float)(TTAB - 1));
        float dd = d - (float)g * step;
        gs[r][g] = expf(coeff * dd * dd);
    }
    __syncthreads();
    int f = threadIdx.x;
    float b = mlp_b1[l * HDIM + f];
    #pragma unroll 1
    for (int r = 0; r < S1ROWS; r++) {
        float s = b;
        #pragma unroll
        for (int g = 0; g < NGAUSS; g++) s += gs[r][g] * w1s[g][f];
        U[(l * TTAB + t0 + r) * HDIM + f] = sspf(s);
    }
}

// ------------------- scale table rows by cosine cutoff C(d) -------------------
__global__ void k_scaleC(float* __restrict__ tab) {
    int idx = blockIdx.x * blockDim.x + threadIdx.x;
    if (idx >= NLAYER * TTAB * HDIM) return;
    int row = (idx >> 7) % TTAB;
    float d = (float)row * (DCUT / (float)(TTAB - 1));
    float C = 0.5f * (cosf(d * 3.14159265358979f / 10.0f) + 1.0f);
    tab[idx] *= C;
}

// ------------------- SGEMM: C = A[M,128] @ B[128,128] (+bias)(ssp)(+res) -------------------
__global__ void __launch_bounds__(256) k_sgemm(
    const float* __restrict__ A, const float* __restrict__ B,
    const float* __restrict__ bias, const float* __restrict__ res,
    float* __restrict__ C, int M, int applySSP) {
    __shared__ float As[16][132];
    __shared__ float Bs[16][128];
    int tid = threadIdx.x;
    int tx = tid & 15, ty = tid >> 4;
    int row0 = blockIdx.x * 128;
    float acc[8][8];
    #pragma unroll
    for (int i = 0; i < 8; i++)
        #pragma unroll
        for (int j = 0; j < 8; j++) acc[i][j] = 0.0f;

    for (int kc = 0; kc < 128; kc += 16) {
        #pragma unroll
        for (int i = 0; i < 2; i++) {
            int r = (tid >> 2) + i * 64;
            int k4 = (tid & 3) * 4;
            float4 v = make_float4(0.f, 0.f, 0.f, 0.f);
            int gr = row0 + r;
            if (gr < M) v = *(const float4*)(A + (size_t)gr * 128 + kc + k4);
            As[k4 + 0][r] = v.x; As[k4 + 1][r] = v.y;
            As[k4 + 2][r] = v.z; As[k4 + 3][r] = v.w;
        }
        #pragma unroll
        for (int i = 0; i < 2; i++) {
            int kk = (tid >> 5) + i * 8;
            int c4 = (tid & 31) * 4;
            *(float4*)&Bs[kk][c4] = *(const float4*)(B + (kc + kk) * 128 + c4);
        }
        __syncthreads();
        #pragma unroll
        for (int kk = 0; kk < 16; kk++) {
            float a[8], b[8];
            *(float4*)&a[0] = *(float4*)&As[kk][ty * 8];
            *(float4*)&a[4] = *(float4*)&As[kk][ty * 8 + 4];
            *(float4*)&b[0] = *(float4*)&Bs[kk][tx * 8];
            *(float4*)&b[4] = *(float4*)&Bs[kk][tx * 8 + 4];
            #pragma unroll
            for (int i = 0; i < 8; i++)
                #pragma unroll
                for (int j = 0; j < 8; j++) acc[i][j] += a[i] * b[j];
        }
        __syncthreads();
    }
    #pragma unroll
    for (int i = 0; i < 8; i++) {
        int gr = row0 + ty * 8 + i;
        if (gr >= M) break;
        float out[8];
        #pragma unroll
        for (int j = 0; j < 8; j++) {
            float c = acc[i][j];
            if (bias) c += bias[tx * 8 + j];
            if (applySSP) c = sspf(c);
            if (res) c += res[(size_t)gr * 128 + tx * 8 + j];
            out[j] = c;
        }
        *(float4*)(C + (size_t)gr * 128 + tx * 8) = *(float4*)&out[0];
        *(float4*)(C + (size_t)gr * 128 + tx * 8 + 4) = *(float4*)&out[4];
    }
}

// ------------------- edge aggregation: warp per node, lerp W from table -------------------
__global__ void k_edge(const int* __restrict__ rowptr, const int* __restrict__ src,
                       const float* __restrict__ et, const float* __restrict__ xf,
                       const float* __restrict__ tab, float* __restrict__ agg) {
    int node = blockIdx.x * 8 + (threadIdx.x >> 5);
    if (node >= NATOMS) return;
    int lane = threadIdx.x & 31;
    int s = rowptr[node], e = rowptr[node + 1];
    float4 acc = make_float4(0.f, 0.f, 0.f, 0.f);
    for (int p = s; p < e; p++) {
        int j = __ldg(&src[p]);
        float t = __ldg(&et[p]);
        int i0 = (int)t;
        float fr = t - (float)i0;
        float4 x  = *(const float4*)(xf  + (size_t)j * 128 + lane * 4);
        float4 w0 = *(const float4*)(tab + (size_t)i0 * 128 + lane * 4);
        float4 w1 = *(const float4*)(tab + (size_t)i0 * 128 + 128 + lane * 4);
        acc.x += x.x * (w0.x + fr * (w1.x - w0.x));
        acc.y += x.y * (w0.y + fr * (w1.y - w0.y));
        acc.z += x.z * (w0.z + fr * (w1.z - w0.z));
        acc.w += x.w * (w0.w + fr * (w1.w - w0.w));
    }
    *(float4*)(agg + (size_t)node * 128 + lane * 4) = acc;
}

// ------------------- molecule pooling (atom_to_conf sorted → run-length) -------------------
#define MCHUNK 256
__global__ void k_molsum(const float* __restrict__ h2, const int* __restrict__ a2c,
                         const int* __restrict__ c2m, float* __restrict__ mol) {
    int f = threadIdx.x;  // 128
    int a0 = blockIdx.x * MCHUNK;
    int aend = min(a0 + MCHUNK, NATOMS);
    int curm = -1;
    float acc = 0.0f;
    for (int a = a0; a < aend; a++) {
        int m = __ldg(&c2m[__ldg(&a2c[a])]);
        if (m != curm) {
            if (curm >= 0) atomicAdd(&mol[curm * 128 + f], acc);
            curm = m;
            acc = 0.0f;
        }
        acc += h2[(size_t)a * 128 + f];
    }
    if (curm >= 0) atomicAdd(&mol[curm * 128 + f], acc);
}

// ------------------- head MLP -------------------
__global__ void k_head(const float* __restrict__ mol, const float* __restrict__ w1,
                       const float* __restrict__ b1, const float* __restrict__ w2,
                       const float* __restrict__ b2, float* __restrict__ out) {
    __shared__ float red[64];
    int m = blockIdx.x;
    int j = threadIdx.x;  // 64
    float s = b1[j];
    for (int f = 0; f < 128; f++) s += mol[m * 128 + f] * w1[f * 64 + j];
    red[j] = sspf(s) * w2[j];
    __syncthreads();
    for (int off = 32; off > 0; off >>= 1) {
        if (j < off) red[j] += red[j + off];
        __syncthreads();
    }
    if (j == 0) out[m] = red[0] + b2[0];
}

// ------------------- launch -------------------
extern "C" void kernel_launch(void* const* d_in, const int* in_sizes, int n_in,
                              void* d_out, int out_size) {
    const int*   z     = (const int*)d_in[0];
    const float* pos   = (const float*)d_in[1];
    const int*   erow  = (const int*)d_in[2];
    const int*   ecol  = (const int*)d_in[3];
    const int*   a2c   = (const int*)d_in[4];
    const int*   c2m   = (const int*)d_in[5];
    const float* emb   = (const float*)d_in[6];
    const float* mw1   = (const float*)d_in[7];
    const float* mb1   = (const float*)d_in[8];
    const float* mw2   = (const float*)d_in[9];
    const float* mb2   = (const float*)d_in[10];
    const float* cl1w  = (const float*)d_in[11];
    const float* cl2w  = (const float*)d_in[12];
    const float* cl2b  = (const float*)d_in[13];
    const float* ilw   = (const float*)d_in[14];
    const float* ilb   = (const float*)d_in[15];
    const float* l1w   = (const float*)d_in[16];
    const float* l1b   = (const float*)d_in[17];
    const float* l2w   = (const float*)d_in[18];
    const float* l2b   = (const float*)d_in[19];
    const float* hw1   = (const float*)d_in[20];
    const float* hb1   = (const float*)d_in[21];
    const float* hw2   = (const float*)d_in[22];
    const float* hb2   = (const float*)d_in[23];
    float* out = (float*)d_out;

    float *ph, *pxf, *pagg, *pu, *pU, *ptab, *pt, *pet, *pmol;
    int *pcnt, *prow, *pcur, *psrc;
    cudaGetSymbolAddress((void**)&ph, g_h);
    cudaGetSymbolAddress((void**)&pxf, g_xf);
    cudaGetSymbolAddress((void**)&pagg, g_agg);
    cudaGetSymbolAddress((void**)&pu, g_u);
    cudaGetSymbolAddress((void**)&pU, g_U);
    cudaGetSymbolAddress((void**)&ptab, g_tab);
    cudaGetSymbolAddress((void**)&pt, g_t);
    cudaGetSymbolAddress((void**)&pet, g_et);
    cudaGetSymbolAddress((void**)&pcnt, g_cnt);
    cudaGetSymbolAddress((void**)&prow, g_rowptr);
    cudaGetSymbolAddress((void**)&pcur, g_cursor);
    cudaGetSymbolAddress((void**)&psrc, g_src);
    cudaGetSymbolAddress((void**)&pmol, g_mol);

    cudaMemsetAsync(pcnt, 0, NATOMS * sizeof(int));
    cudaMemsetAsync(pmol, 0, NMOL * HDIM * sizeof(float));

    // embedding
    k_embed<<<(NATOMS * HDIM + 255) / 256, 256>>>(z, emb, ph);
    // graph preprocessing
    k_dist<<<(NEDGE + 255) / 256, 256>>>(pos, erow, ecol, pt, pcnt);
    k_scan<<<1, 1024>>>(pcnt, prow, pcur);
    k_fill<<<(NEDGE + 255) / 256, 256>>>(erow, ecol, pt, pcur, psrc, pet);
    // filter tables
    k_stage1<<<NLAYER * (TTAB / S1ROWS), 128>>>(mw1, mb1, pU);
    for (int l = 0; l < NLAYER; l++) {
        k_sgemm<<<TTAB / 128, 256>>>(pU + (size_t)l * TTAB * 128, mw2 + l * 128 * 128,
                                     mb2 + l * 128, nullptr,
                                     ptab + (size_t)l * TTAB * 128, TTAB, 0);
    }
    k_scaleC<<<(NLAYER * TTAB * HDIM + 255) / 256, 256>>>(ptab);

    const int gemmBlocks = (NATOMS + 127) / 128;
    for (int l = 0; l < NLAYER; l++) {
        // xf = h @ conv_lin1_w[l]
        k_sgemm<<<gemmBlocks, 256>>>(ph, cl1w + l * 128 * 128, nullptr, nullptr, pxf, NATOMS, 0);
        // agg = scatter_sum(xf[row] * W)
        k_edge<<<(NATOMS + 7) / 8, 256>>>(prow, psrc, pet, pxf,
                                          ptab + (size_t)l * TTAB * 128, pagg);
        // u = ssp(agg @ conv_lin2_w[l] + b)
        k_sgemm<<<gemmBlocks, 256>>>(pagg, cl2w + l * 128 * 128, cl2b + l * 128, nullptr,
                                     pu, NATOMS, 1);
        // h = h + u @ int_lin_w[l] + b
        k_sgemm<<<gemmBlocks, 256>>>(pu, ilw + l * 128 * 128, ilb + l * 128, ph, ph, NATOMS, 0);
    }
    // final node MLP
    k_sgemm<<<gemmBlocks, 256>>>(ph, l1w, l1b, nullptr, pxf, NATOMS, 1);
    k_sgemm<<<gemmBlocks, 256>>>(pxf, l2w, l2b, nullptr, pagg, NATOMS, 0);
    // pooling + head
    k_molsum<<<(NATOMS + MCHUNK - 1) / MCHUNK, 128>>>(pagg, a2c, c2m, pmol);
    k_head<<<NMOL, 64>>>(pmol, hw1, hb1, hw2, hb2, out);
}

// round 2
// speedup vs baseline: 1.7139x; 1.7139x over previous
#include <cuda_runtime.h>
#include <cuda_bf16.h>
#include <math.h>

#define NATOMS 50000
#define NEDGE  600000
#define HDIM   128
#define NGAUSS 50
#define NLAYER 6
#define NCONF  500
#define NMOL   100
#define TTAB   8192
#define DCUT   13.0f

// ------------------- static device scratch (no allocs allowed) -------------------
__device__ float g_h[NATOMS * HDIM];
__device__ float g_xf[NATOMS * HDIM];
__device__ float g_agg[NATOMS * HDIM];
__device__ float g_u[NATOMS * HDIM];
__device__ float g_U[NLAYER * TTAB * HDIM];    // ssp(gauss@w1+b1)
__device__ float g_tab[NLAYER * TTAB * HDIM];  // W table (incl. cosine cutoff)
__device__ float g_t[NEDGE];                   // table position per edge, -1 = inactive
__device__ int   g_cnt[NATOMS];
__device__ int   g_rowptr[NATOMS + 1];
__device__ int   g_cursor[NATOMS];
__device__ int   g_src[NEDGE];
__device__ float g_et[NEDGE];
__device__ float g_mol[NMOL * HDIM];

__device__ __forceinline__ float sspf(float x) {
    return fmaxf(x, 0.0f) + log1pf(expf(-fabsf(x))) - 0.69314718055994531f;
}

__device__ __forceinline__ unsigned f2tf(float f) {
    unsigned r;
    asm("cvt.rna.tf32.f32 %0, %1;" : "=r"(r) : "f"(f));
    return r;
}

// ------------------- embedding gather -------------------
__global__ void k_embed(const int* __restrict__ z, const float* __restrict__ emb,
                        float* __restrict__ h) {
    int idx = blockIdx.x * blockDim.x + threadIdx.x;
    if (idx >= NATOMS * HDIM) return;
    int a = idx >> 7, f = idx & 127;
    h[idx] = emb[z[a] * HDIM + f];
}

// ------------------- edge distances + histogram -------------------
__global__ void k_dist(const float* __restrict__ pos, const int* __restrict__ erow,
                       const int* __restrict__ ecol, float* __restrict__ tpos,
                       int* __restrict__ cnt) {
    int e = blockIdx.x * blockDim.x + threadIdx.x;
    if (e >= NEDGE) return;
    int r = erow[e], c = ecol[e];
    float dx = pos[r * 3 + 0] - pos[c * 3 + 0];
    float dy = pos[r * 3 + 1] - pos[c * 3 + 1];
    float dz = pos[r * 3 + 2] - pos[c * 3 + 2];
    float d = sqrtf(dx * dx + dy * dy + dz * dz);
    if (d < DCUT) {
        tpos[e] = d * ((float)(TTAB - 1) / DCUT);
        atomicAdd(&cnt[c], 1);
    } else {
        tpos[e] = -1.0f;
    }
}

// ------------------- single-block exclusive scan over N counts -------------------
__global__ void k_scan(const int* __restrict__ cnt, int* __restrict__ rowptr,
                       int* __restrict__ cursor) {
    __shared__ int sm[1024];
    __shared__ int base_s;
    int tid = threadIdx.x;
    if (tid == 0) base_s = 0;
    __syncthreads();
    for (int c0 = 0; c0 < NATOMS; c0 += 1024) {
        int i = c0 + tid;
        int v = (i < NATOMS) ? cnt[i] : 0;
        sm[tid] = v;
        __syncthreads();
        for (int off = 1; off < 1024; off <<= 1) {
            int t = (tid >= off) ? sm[tid - off] : 0;
            __syncthreads();
            sm[tid] += t;
            __syncthreads();
        }
        int incl = sm[tid];
        int base = base_s;
        if (i < NATOMS) {
            int ex = base + incl - v;
            rowptr[i] = ex;
            cursor[i] = ex;
        }
        __syncthreads();
        if (tid == 1023) base_s = base + incl;
        __syncthreads();
    }
    if (tid == 0) rowptr[NATOMS] = base_s;
}

// ------------------- CSR fill -------------------
__global__ void k_fill(const int* __restrict__ erow, const int* __restrict__ ecol,
                       const float* __restrict__ tpos, int* __restrict__ cursor,
                       int* __restrict__ src, float* __restrict__ et) {
    int e = blockIdx.x * blockDim.x + threadIdx.x;
    if (e >= NEDGE) return;
    float t = tpos[e];
    if (t >= 0.0f) {
        int c = ecol[e];
        int p = atomicAdd(&cursor[c], 1);
        src[p] = erow[e];
        et[p] = t;
    }
}

// ------------------- filter table stage1: U = ssp(gauss @ w1 + b1) -------------------
#define S1ROWS 16
__global__ void k_stage1(const float* __restrict__ mlp_w1, const float* __restrict__ mlp_b1,
                         float* __restrict__ U) {
    __shared__ float w1s[NGAUSS][HDIM];
    __shared__ float gs[S1ROWS][NGAUSS];
    const int blocksPerLayer = TTAB / S1ROWS;
    int l = blockIdx.x / blocksPerLayer;
    int t0 = (blockIdx.x % blocksPerLayer) * S1ROWS;
    const float* w1 = mlp_w1 + l * NGAUSS * HDIM;
    for (int i = threadIdx.x; i < NGAUSS * HDIM; i += blockDim.x)
        w1s[i / HDIM][i % HDIM] = w1[i];
    const float step = 10.0f / 49.0f;
    const float coeff = -0.5f / (step * step);
    for (int i = threadIdx.x; i < S1ROWS * NGAUSS; i += blockDim.x) {
        int r = i / NGAUSS, g = i % NGAUSS;
        float d = (float)(t0 + r) * (DCUT / (float)(TTAB - 1));
        float dd = d - (float)g * step;
        gs[r][g] = expf(coeff * dd * dd);
    }
    __syncthreads();
    int f = threadIdx.x;
    float b = mlp_b1[l * HDIM + f];
    #pragma unroll 1
    for (int r = 0; r < S1ROWS; r++) {
        float s = b;
        #pragma unroll
        for (int g = 0; g < NGAUSS; g++) s += gs[r][g] * w1s[g][f];
        U[(l * TTAB + t0 + r) * HDIM + f] = sspf(s);
    }
}

// ------------------- scale table rows by cosine cutoff C(d) -------------------
__global__ void k_scaleC(float* __restrict__ tab) {
    int idx = blockIdx.x * blockDim.x + threadIdx.x;
    if (idx >= NLAYER * TTAB * HDIM) return;
    int row = (idx >> 7) % TTAB;
    float d = (float)row * (DCUT / (float)(TTAB - 1));
    float C = 0.5f * (cosf(d * 3.14159265358979f / 10.0f) + 1.0f);
    tab[idx] *= C;
}

// ------------------- tf32 tensor-core GEMM: C = A[M,128] @ B[128,128] -------------------
// block tile 128x128, 8 warps (4 in M x 2 in N), warp tile 32x64.
// A smem [128][36] f32 (ld=36 -> frag-load bank = lane, conflict-free)
// B smem [32][136] f32 (ld=136 -> frag-load bank = 8*tig+gid, conflict-free)
// cvt.rna f32->tf32 at fragment load.
__global__ void __launch_bounds__(256) k_tgemm(
    const float* __restrict__ A, const float* __restrict__ B,
    const float* __restrict__ bias, const float* __restrict__ res,
    float* __restrict__ C, int M, int applySSP) {
    __shared__ float As[128][36];
    __shared__ float Bs[32][136];
    int tid = threadIdx.x;
    int lane = tid & 31, warp = tid >> 5;
    int gid = lane >> 2, tig = lane & 3;
    int warpM = warp & 3, warpN = warp >> 2;
    int row0 = blockIdx.x * 128;

    float c[2][8][4];
    #pragma unroll
    for (int mi = 0; mi < 2; mi++)
        #pragma unroll
        for (int nj = 0; nj < 8; nj++)
            #pragma unroll
            for (int q = 0; q < 4; q++) c[mi][nj][q] = 0.0f;

    for (int kc = 0; kc < 4; kc++) {
        if (kc) __syncthreads();
        // load A chunk: 128 rows x 32 cols (float4 per thread x4)
        #pragma unroll
        for (int i = 0; i < 4; i++) {
            int idx = tid + i * 256;          // 0..1023
            int r = idx >> 3, c4 = (idx & 7) * 4;
            float4 v = make_float4(0.f, 0.f, 0.f, 0.f);
            int gr = row0 + r;
            if (gr < M) v = *(const float4*)(A + (size_t)gr * 128 + kc * 32 + c4);
            *(float4*)&As[r][c4] = v;
        }
        // load B chunk: 32 rows x 128 cols
        #pragma unroll
        for (int i = 0; i < 4; i++) {
            int idx = tid + i * 256;
            int r = idx >> 5, c4 = (idx & 31) * 4;
            float4 v = *(const float4*)(B + (size_t)(kc * 32 + r) * 128 + c4);
            *(float4*)&Bs[r][c4] = v;
        }
        __syncthreads();
        #pragma unroll
        for (int ks = 0; ks < 4; ks++) {
            int k0 = ks * 8;
            unsigned a[2][4], b[8][2];
            #pragma unroll
            for (int mi = 0; mi < 2; mi++) {
                int mw = warpM * 32 + mi * 16 + gid;
                a[mi][0] = f2tf(As[mw][k0 + tig]);
                a[mi][1] = f2tf(As[mw + 8][k0 + tig]);
                a[mi][2] = f2tf(As[mw][k0 + tig + 4]);
                a[mi][3] = f2tf(As[mw + 8][k0 + tig + 4]);
            }
            #pragma unroll
            for (int nj = 0; nj < 8; nj++) {
                int nb = warpN * 64 + nj * 8 + gid;
                b[nj][0] = f2tf(Bs[k0 + tig][nb]);
                b[nj][1] = f2tf(Bs[k0 + tig + 4][nb]);
            }
            #pragma unroll
            for (int mi = 0; mi < 2; mi++)
                #pragma unroll
                for (int nj = 0; nj < 8; nj++) {
                    asm volatile(
                        "mma.sync.aligned.m16n8k8.row.col.f32.tf32.tf32.f32 "
                        "{%0,%1,%2,%3}, {%4,%5,%6,%7}, {%8,%9}, {%0,%1,%2,%3};"
                        : "+f"(c[mi][nj][0]), "+f"(c[mi][nj][1]),
                          "+f"(c[mi][nj][2]), "+f"(c[mi][nj][3])
                        : "r"(a[mi][0]), "r"(a[mi][1]), "r"(a[mi][2]), "r"(a[mi][3]),
                          "r"(b[nj][0]), "r"(b[nj][1]));
                }
        }
    }
    // epilogue: c0/c1 -> (row=gid, col=2*tig,2*tig+1), c2/c3 -> row+8
    #pragma unroll
    for (int mi = 0; mi < 2; mi++) {
        #pragma unroll
        for (int half = 0; half < 2; half++) {
            int gr = row0 + warpM * 32 + mi * 16 + half * 8 + gid;
            if (gr < M) {
                #pragma unroll
                for (int nj = 0; nj < 8; nj++) {
                    int col = warpN * 64 + nj * 8 + tig * 2;
                    float v0 = c[mi][nj][half * 2 + 0];
                    float v1 = c[mi][nj][half * 2 + 1];
                    if (bias) { v0 += bias[col]; v1 += bias[col + 1]; }
                    if (applySSP) { v0 = sspf(v0); v1 = sspf(v1); }
                    if (res) {
                        float2 rr = *(const float2*)(res + (size_t)gr * 128 + col);
                        v0 += rr.x; v1 += rr.y;
                    }
                    float2 o = make_float2(v0, v1);
                    *(float2*)(C + (size_t)gr * 128 + col) = o;
                }
            }
        }
    }
}

// ------------------- edge aggregation: warp per node, lerp W from table -------------------
__global__ void k_edge(const int* __restrict__ rowptr, const int* __restrict__ src,
                       const float* __restrict__ et, const float* __restrict__ xf,
                       const float* __restrict__ tab, float* __restrict__ agg) {
    int node = blockIdx.x * 8 + (threadIdx.x >> 5);
    if (node >= NATOMS) return;
    int lane = threadIdx.x & 31;
    int s = rowptr[node], e = rowptr[node + 1];
    float4 acc = make_float4(0.f, 0.f, 0.f, 0.f);
    for (int p = s; p < e; p++) {
        int j = __ldg(&src[p]);
        float t = __ldg(&et[p]);
        int i0 = (int)t;
        float fr = t - (float)i0;
        float4 x  = *(const float4*)(xf  + (size_t)j * 128 + lane * 4);
        float4 w0 = *(const float4*)(tab + (size_t)i0 * 128 + lane * 4);
        float4 w1 = *(const float4*)(tab + (size_t)i0 * 128 + 128 + lane * 4);
        acc.x += x.x * (w0.x + fr * (w1.x - w0.x));
        acc.y += x.y * (w0.y + fr * (w1.y - w0.y));
        acc.z += x.z * (w0.z + fr * (w1.z - w0.z));
        acc.w += x.w * (w0.w + fr * (w1.w - w0.w));
    }
    *(float4*)(agg + (size_t)node * 128 + lane * 4) = acc;
}

// ------------------- molecule pooling (atom_to_conf sorted -> run-length) -------------------
#define MCHUNK 256
__global__ void k_molsum(const float* __restrict__ h2, const int* __restrict__ a2c,
                         const int* __restrict__ c2m, float* __restrict__ mol) {
    int f = threadIdx.x;  // 128
    int a0 = blockIdx.x * MCHUNK;
    int aend = min(a0 + MCHUNK, NATOMS);
    int curm = -1;
    float acc = 0.0f;
    for (int a = a0; a < aend; a++) {
        int m = __ldg(&c2m[__ldg(&a2c[a])]);
        if (m != curm) {
            if (curm >= 0) atomicAdd(&mol[curm * 128 + f], acc);
            curm = m;
            acc = 0.0f;
        }
        acc += h2[(size_t)a * 128 + f];
    }
    if (curm >= 0) atomicAdd(&mol[curm * 128 + f], acc);
}

// ------------------- head MLP -------------------
__global__ void k_head(const float* __restrict__ mol, const float* __restrict__ w1,
                       const float* __restrict__ b1, const float* __restrict__ w2,
                       const float* __restrict__ b2, float* __restrict__ out) {
    __shared__ float red[64];
    int m = blockIdx.x;
    int j = threadIdx.x;  // 64
    float s = b1[j];
    for (int f = 0; f < 128; f++) s += mol[m * 128 + f] * w1[f * 64 + j];
    red[j] = sspf(s) * w2[j];
    __syncthreads();
    for (int off = 32; off > 0; off >>= 1) {
        if (j < off) red[j] += red[j + off];
        __syncthreads();
    }
    if (j == 0) out[m] = red[0] + b2[0];
}

// ------------------- launch -------------------
extern "C" void kernel_launch(void* const* d_in, const int* in_sizes, int n_in,
                              void* d_out, int out_size) {
    const int*   z     = (const int*)d_in[0];
    const float* pos   = (const float*)d_in[1];
    const int*   erow  = (const int*)d_in[2];
    const int*   ecol  = (const int*)d_in[3];
    const int*   a2c   = (const int*)d_in[4];
    const int*   c2m   = (const int*)d_in[5];
    const float* emb   = (const float*)d_in[6];
    const float* mw1   = (const float*)d_in[7];
    const float* mb1   = (const float*)d_in[8];
    const float* mw2   = (const float*)d_in[9];
    const float* mb2   = (const float*)d_in[10];
    const float* cl1w  = (const float*)d_in[11];
    const float* cl2w  = (const float*)d_in[12];
    const float* cl2b  = (const float*)d_in[13];
    const float* ilw   = (const float*)d_in[14];
    const float* ilb   = (const float*)d_in[15];
    const float* l1w   = (const float*)d_in[16];
    const float* l1b   = (const float*)d_in[17];
    const float* l2w   = (const float*)d_in[18];
    const float* l2b   = (const float*)d_in[19];
    const float* hw1   = (const float*)d_in[20];
    const float* hb1   = (const float*)d_in[21];
    const float* hw2   = (const float*)d_in[22];
    const float* hb2   = (const float*)d_in[23];
    float* out = (float*)d_out;

    float *ph, *pxf, *pagg, *pu, *pU, *ptab, *pt, *pet, *pmol;
    int *pcnt, *prow, *pcur, *psrc;
    cudaGetSymbolAddress((void**)&ph, g_h);
    cudaGetSymbolAddress((void**)&pxf, g_xf);
    cudaGetSymbolAddress((void**)&pagg, g_agg);
    cudaGetSymbolAddress((void**)&pu, g_u);
    cudaGetSymbolAddress((void**)&pU, g_U);
    cudaGetSymbolAddress((void**)&ptab, g_tab);
    cudaGetSymbolAddress((void**)&pt, g_t);
    cudaGetSymbolAddress((void**)&pet, g_et);
    cudaGetSymbolAddress((void**)&pcnt, g_cnt);
    cudaGetSymbolAddress((void**)&prow, g_rowptr);
    cudaGetSymbolAddress((void**)&pcur, g_cursor);
    cudaGetSymbolAddress((void**)&psrc, g_src);
    cudaGetSymbolAddress((void**)&pmol, g_mol);

    cudaMemsetAsync(pcnt, 0, NATOMS * sizeof(int));
    cudaMemsetAsync(pmol, 0, NMOL * HDIM * sizeof(float));

    // embedding
    k_embed<<<(NATOMS * HDIM + 255) / 256, 256>>>(z, emb, ph);
    // graph preprocessing
    k_dist<<<(NEDGE + 255) / 256, 256>>>(pos, erow, ecol, pt, pcnt);
    k_scan<<<1, 1024>>>(pcnt, prow, pcur);
    k_fill<<<(NEDGE + 255) / 256, 256>>>(erow, ecol, pt, pcur, psrc, pet);
    // filter tables
    k_stage1<<<NLAYER * (TTAB / S1ROWS), 128>>>(mw1, mb1, pU);
    for (int l = 0; l < NLAYER; l++) {
        k_tgemm<<<TTAB / 128, 256>>>(pU + (size_t)l * TTAB * 128, mw2 + l * 128 * 128,
                                     mb2 + l * 128, nullptr,
                                     ptab + (size_t)l * TTAB * 128, TTAB, 0);
    }
    k_scaleC<<<(NLAYER * TTAB * HDIM + 255) / 256, 256>>>(ptab);

    const int gemmBlocks = (NATOMS + 127) / 128;
    for (int l = 0; l < NLAYER; l++) {
        // xf = h @ conv_lin1_w[l]
        k_tgemm<<<gemmBlocks, 256>>>(ph, cl1w + l * 128 * 128, nullptr, nullptr, pxf, NATOMS, 0);
        // agg = scatter_sum(xf[row] * W)
        k_edge<<<(NATOMS + 7) / 8, 256>>>(prow, psrc, pet, pxf,
                                          ptab + (size_t)l * TTAB * 128, pagg);
        // u = ssp(agg @ conv_lin2_w[l] + b)
        k_tgemm<<<gemmBlocks, 256>>>(pagg, cl2w + l * 128 * 128, cl2b + l * 128, nullptr,
                                     pu, NATOMS, 1);
        // h = h + u @ int_lin_w[l] + b
        k_tgemm<<<gemmBlocks, 256>>>(pu, ilw + l * 128 * 128, ilb + l * 128, ph, ph, NATOMS, 0);
    }
    // final node MLP
    k_tgemm<<<gemmBlocks, 256>>>(ph, l1w, l1b, nullptr, pxf, NATOMS, 1);
    k_tgemm<<<gemmBlocks, 256>>>(pxf, l2w, l2b, nullptr, pagg, NATOMS, 0);
    // pooling + head
    k_molsum<<<(NATOMS + MCHUNK - 1) / MCHUNK, 128>>>(pagg, a2c, c2m, pmol);
    k_head<<<NMOL, 64>>>(pmol, hw1, hb1, hw2, hb2, out);
}